// round 4
// baseline (speedup 1.0000x reference)
#include <cuda_runtime.h>
#include <math.h>

#define NN 100000
#define NE 1600000
#define IN_DIM 128
#define HID 64
#define OUTD 40
#define NB ((NN + 255) / 256)   // 391 scan blocks

// Scratch — __device__ globals (no allocation APIs allowed).
__device__ float g_A[NN * 64];       // GEMM output (h)
__device__ float g_B[NN * 64];       // conv output / GEMM input
__device__ int   g_src[NE];
__device__ int   g_dst[NE];
__device__ int   g_deg[NN];
__device__ float g_dinv[NN];
__device__ int   g_off[NN];          // CSR row offsets (exclusive)
__device__ int   g_cursor[NN];
__device__ int   g_bsum[512];
__device__ int   g_csr_src[NE];
__device__ float g_csr_norm[NE];
__device__ int   g_is64;

// ---------------- Edge dtype detection + conversion ----------------
// If edge_index is int64 (values < 2^31), every odd 32-bit word is 0.
// If it is int32 (uniform [0, NN)), odd words are ~never 0.
__global__ void detect_kernel(const int* __restrict__ ei32) {
    int t = threadIdx.x;
    int zeros = 0;
    for (int i = t; i < 2048; i += 32)
        if (ei32[2 * i + 1] == 0) zeros++;
#pragma unroll
    for (int o = 16; o; o >>= 1) zeros += __shfl_xor_sync(0xffffffffu, zeros, o);
    if (t == 0) g_is64 = (zeros > 1536) ? 1 : 0;
}

__global__ void convert_kernel(const void* __restrict__ ei) {
    int e = blockIdx.x * blockDim.x + threadIdx.x;
    if (e >= NE) return;
    int s, d;
    if (g_is64) {
        const long long* p = (const long long*)ei;
        s = (int)p[e];
        d = (int)p[(size_t)NE + e];
    } else {
        const int* p = (const int*)ei;
        s = p[e];
        d = p[NE + e];
    }
    g_src[e] = s;
    g_dst[e] = d;
}

// ---------------- CSR build ----------------

__global__ void zero_deg() {
    int i = blockIdx.x * blockDim.x + threadIdx.x;
    if (i < NN) g_deg[i] = 0;
}

__global__ void deg_kernel() {
    int i = blockIdx.x * blockDim.x + threadIdx.x;
    if (i >= NE) return;
    int d = g_dst[i];
    if ((unsigned)d < NN && (unsigned)g_src[i] < NN)
        atomicAdd(&g_deg[d], 1);
}

__global__ void dinv_kernel() {
    int i = blockIdx.x * blockDim.x + threadIdx.x;
    if (i < NN) g_dinv[i] = rsqrtf((float)g_deg[i] + 1.0f);  // +1 = self-loop
}

// Exclusive scan of g_deg -> g_off (3 phases).
__global__ void scan1() {
    __shared__ int sh[256];
    int t = threadIdx.x, i = blockIdx.x * 256 + t;
    int v = (i < NN) ? g_deg[i] : 0;
    sh[t] = v;
    __syncthreads();
    for (int off = 1; off < 256; off <<= 1) {
        int x = (t >= off) ? sh[t - off] : 0;
        __syncthreads();
        sh[t] += x;
        __syncthreads();
    }
    if (i < NN) g_off[i] = sh[t] - v;
    if (t == 255) g_bsum[blockIdx.x] = sh[255];
}

__global__ void scan2() {
    __shared__ int sh[512];
    int t = threadIdx.x;
    int v = (t < NB) ? g_bsum[t] : 0;
    sh[t] = v;
    __syncthreads();
    for (int off = 1; off < 512; off <<= 1) {
        int x = (t >= off) ? sh[t - off] : 0;
        __syncthreads();
        sh[t] += x;
        __syncthreads();
    }
    if (t < NB) g_bsum[t] = sh[t] - v;
}

__global__ void scan3() {
    int i = blockIdx.x * blockDim.x + threadIdx.x;
    if (i < NN) {
        int o = g_off[i] + g_bsum[i >> 8];
        g_off[i] = o;
        g_cursor[i] = o;
    }
}

__global__ void fill_kernel() {
    int e = blockIdx.x * blockDim.x + threadIdx.x;
    if (e >= NE) return;
    int s = g_src[e];
    int d = g_dst[e];
    if ((unsigned)s >= NN || (unsigned)d >= NN) return;
    int pos = atomicAdd(&g_cursor[d], 1);
    g_csr_src[pos] = s;
    g_csr_norm[pos] = g_dinv[s] * g_dinv[d];
}

// ---------------- GEMM: g_A[M,64] = X[M,K] @ W[K,64] ----------------
// 256 threads / 32 rows per block; thread computes 2 rows x 4 cols.
// PAD=0 for K=128 keeps static smem at exactly 48KB.

template <int K, bool FROMB>
__global__ __launch_bounds__(256) void gemm64(
    const float* __restrict__ Xin, const float* __restrict__ W, int M)
{
    constexpr int PAD = (K == 128) ? 0 : 4;
    const float* __restrict__ X = FROMB ? (const float*)g_B : Xin;
    __shared__ float Ws[K * 64];
    __shared__ float Xs[32 * (K + PAD)];
    const int tid = threadIdx.x;

    for (int i = tid; i < K * 64; i += 256) Ws[i] = W[i];
    const int r0 = blockIdx.x * 32;
    for (int i = tid; i < 32 * K; i += 256) {
        int r = i / K, k = i - r * K;
        int gr = r0 + r;
        Xs[r * (K + PAD) + k] = (gr < M) ? X[(size_t)gr * K + k] : 0.f;
    }
    __syncthreads();

    const int cx = tid & 15;
    const int ry = tid >> 4;
    const float* x0p = &Xs[(2 * ry) * (K + PAD)];
    const float* x1p = &Xs[(2 * ry + 1) * (K + PAD)];

    float4 a0 = make_float4(0.f, 0.f, 0.f, 0.f);
    float4 a1 = make_float4(0.f, 0.f, 0.f, 0.f);
#pragma unroll 8
    for (int k = 0; k < K; k++) {
        float4 w = *(const float4*)&Ws[k * 64 + cx * 4];
        float x0 = x0p[k], x1 = x1p[k];
        a0.x = fmaf(x0, w.x, a0.x); a0.y = fmaf(x0, w.y, a0.y);
        a0.z = fmaf(x0, w.z, a0.z); a0.w = fmaf(x0, w.w, a0.w);
        a1.x = fmaf(x1, w.x, a1.x); a1.y = fmaf(x1, w.y, a1.y);
        a1.z = fmaf(x1, w.z, a1.z); a1.w = fmaf(x1, w.w, a1.w);
    }
    const int r = r0 + 2 * ry;
    if (r < M)     *(float4*)&g_A[(size_t)r * 64 + cx * 4] = a0;
    if (r + 1 < M) *(float4*)&g_A[(size_t)(r + 1) * 64 + cx * 4] = a1;
}

// ---------------- Gather + self-loop + bias (+ReLU): g_B = conv(g_A) ----------------
// One warp per destination node; lane owns dims {lane, lane+32}.

__global__ __launch_bounds__(256) void gather_kernel(const float* __restrict__ b, int relu)
{
    int node = (blockIdx.x * blockDim.x + threadIdx.x) >> 5;
    int lane = threadIdx.x & 31;
    if (node >= NN) return;

    int beg = g_off[node];
    int end = beg + g_deg[node];

    float a0 = 0.f, a1 = 0.f;
    int s = 0; float nn = 0.f;
    if (beg < end) { s = g_csr_src[beg]; nn = g_csr_norm[beg]; }
    for (int j = beg; j < end; j++) {
        int s2 = 0; float nn2 = 0.f;
        if (j + 1 < end) { s2 = __ldg(&g_csr_src[j + 1]); nn2 = __ldg(&g_csr_norm[j + 1]); }
        const float* hp = &g_A[(size_t)s * 64];
        a0 = fmaf(hp[lane], nn, a0);
        a1 = fmaf(hp[32 + lane], nn, a1);
        s = s2; nn = nn2;
    }

    float di = g_dinv[node];
    float self = di * di;
    const float* hn = &g_A[(size_t)node * 64];
    a0 = fmaf(hn[lane], self, a0) + b[lane];
    a1 = fmaf(hn[32 + lane], self, a1) + b[32 + lane];
    if (relu) { a0 = fmaxf(a0, 0.f); a1 = fmaxf(a1, 0.f); }

    g_B[(size_t)node * 64 + lane] = a0;
    g_B[(size_t)node * 64 + 32 + lane] = a1;
}

// ---------------- Head: out = log_softmax(g_B @ Wl + bl) ----------------

__global__ __launch_bounds__(256) void head_kernel(
    const float* __restrict__ Wl, const float* __restrict__ bl,
    float* __restrict__ out, int M)
{
    __shared__ float Wls[64 * OUTD];
    __shared__ float bls[OUTD];
    __shared__ float rowS[8][64];
    const int tid = threadIdx.x;
    for (int i = tid; i < 64 * OUTD; i += 256) Wls[i] = Wl[i];
    if (tid < OUTD) bls[tid] = bl[tid];
    __syncthreads();

    const int w = tid >> 5, lane = tid & 31;
    const int row = blockIdx.x * 8 + w;
    if (row >= M) return;

    rowS[w][lane]      = g_B[(size_t)row * 64 + lane];
    rowS[w][32 + lane] = g_B[(size_t)row * 64 + 32 + lane];
    __syncwarp();

    float acc0 = bls[lane];
    float acc1 = (lane < 8) ? bls[32 + lane] : 0.f;
#pragma unroll
    for (int k = 0; k < 64; k++) {
        float ek = rowS[w][k];
        acc0 = fmaf(ek, Wls[k * OUTD + lane], acc0);
        if (lane < 8) acc1 = fmaf(ek, Wls[k * OUTD + 32 + lane], acc1);
    }

    float m = acc0;
    if (lane < 8) m = fmaxf(m, acc1);
#pragma unroll
    for (int off = 16; off; off >>= 1) m = fmaxf(m, __shfl_xor_sync(0xffffffffu, m, off));
    float sum = expf(acc0 - m) + ((lane < 8) ? expf(acc1 - m) : 0.f);
#pragma unroll
    for (int off = 16; off; off >>= 1) sum += __shfl_xor_sync(0xffffffffu, sum, off);
    float lse = m + logf(sum);

    out[(size_t)row * OUTD + lane] = acc0 - lse;
    if (lane < 8) out[(size_t)row * OUTD + 32 + lane] = acc1 - lse;
}

// ---------------- Launch ----------------

extern "C" void kernel_launch(void* const* d_in, const int* in_sizes, int n_in,
                              void* d_out, int out_size)
{
    const float* x  = (const float*)d_in[0];
    const void*  ei = d_in[1];
    const float* W1 = (const float*)d_in[2];
    const float* b1 = (const float*)d_in[3];
    const float* W2 = (const float*)d_in[4];
    const float* b2 = (const float*)d_in[5];
    const float* Wl = (const float*)d_in[6];
    const float* bl = (const float*)d_in[7];
    float* out = (float*)d_out;

    const int M = NN;
    const int NBLK = (NN + 255) / 256;
    const int EBLK = (NE + 255) / 256;

    // Edge dtype detection + int32 materialization
    detect_kernel<<<1, 32>>>((const int*)ei);
    convert_kernel<<<EBLK, 256>>>(ei);

    // CSR build (graph shared by both layers)
    zero_deg<<<NBLK, 256>>>();
    deg_kernel<<<EBLK, 256>>>();
    dinv_kernel<<<NBLK, 256>>>();
    scan1<<<NB, 256>>>();
    scan2<<<1, 512>>>();
    scan3<<<NBLK, 256>>>();
    fill_kernel<<<EBLK, 256>>>();

    // Layer 1
    gemm64<IN_DIM, false><<<(M + 31) / 32, 256>>>(x, W1, M);
    gather_kernel<<<(M * 32 + 255) / 256, 256>>>(b1, 1);

    // Layer 2
    gemm64<HID, true><<<(M + 31) / 32, 256>>>(nullptr, W2, M);
    gather_kernel<<<(M * 32 + 255) / 256, 256>>>(b2, 0);

    // Head
    head_kernel<<<(M + 7) / 8, 256>>>(Wl, bl, out, M);
}

// round 5
// speedup vs baseline: 1.0090x; 1.0090x over previous
#include <cuda_runtime.h>
#include <cuda_fp16.h>
#include <math.h>

#define NN 100000
#define NE 1600000
#define IN_DIM 128
#define HID 64
#define OUTD 40
#define NB ((NN + 255) / 256)   // 391 scan blocks

// Scratch — __device__ globals (no allocation APIs allowed).
__device__ __half2 g_Ah[NN * 32];    // GEMM output h in fp16 (64 dims = 32 half2)
__device__ float   g_B[NN * 64];     // conv output / GEMM input (fp32)
__device__ int     g_src[NE];
__device__ int     g_dst[NE];
__device__ int     g_deg[NN];
__device__ float   g_dinv[NN];
__device__ int     g_off[NN];        // CSR row offsets (exclusive)
__device__ int     g_cursor[NN];
__device__ int     g_bsum[512];
__device__ int     g_csr_src[NE];
__device__ float   g_csr_norm[NE];
__device__ int     g_is64;

// ---------------- Edge dtype detection ----------------
// int64 indices < 2^31 => every odd 32-bit word is 0; int32 uniform => never.
__global__ void detect_kernel(const int* __restrict__ ei32) {
    int t = threadIdx.x;
    int zeros = 0;
    for (int i = t; i < 2048; i += 32)
        if (ei32[2 * i + 1] == 0) zeros++;
#pragma unroll
    for (int o = 16; o; o >>= 1) zeros += __shfl_xor_sync(0xffffffffu, zeros, o);
    if (t == 0) g_is64 = (zeros > 1536) ? 1 : 0;
}

// ---------------- Fused convert + degree count ----------------
__global__ void convdeg_kernel(const void* __restrict__ ei) {
    int e = blockIdx.x * blockDim.x + threadIdx.x;
    if (e >= NE) return;
    int s, d;
    if (g_is64) {
        const long long* p = (const long long*)ei;
        s = (int)p[e];
        d = (int)p[(size_t)NE + e];
    } else {
        const int* p = (const int*)ei;
        s = p[e];
        d = p[NE + e];
    }
    g_src[e] = s;
    g_dst[e] = d;
    if ((unsigned)d < NN && (unsigned)s < NN) atomicAdd(&g_deg[d], 1);
}

__global__ void zero_deg() {
    int i = blockIdx.x * blockDim.x + threadIdx.x;
    if (i < NN) g_deg[i] = 0;
}

__global__ void dinv_kernel() {
    int i = blockIdx.x * blockDim.x + threadIdx.x;
    if (i < NN) g_dinv[i] = rsqrtf((float)g_deg[i] + 1.0f);  // +1 = self-loop
}

// Exclusive scan of g_deg -> g_off (3 phases).
__global__ void scan1() {
    __shared__ int sh[256];
    int t = threadIdx.x, i = blockIdx.x * 256 + t;
    int v = (i < NN) ? g_deg[i] : 0;
    sh[t] = v;
    __syncthreads();
    for (int off = 1; off < 256; off <<= 1) {
        int x = (t >= off) ? sh[t - off] : 0;
        __syncthreads();
        sh[t] += x;
        __syncthreads();
    }
    if (i < NN) g_off[i] = sh[t] - v;
    if (t == 255) g_bsum[blockIdx.x] = sh[255];
}

__global__ void scan2() {
    __shared__ int sh[512];
    int t = threadIdx.x;
    int v = (t < NB) ? g_bsum[t] : 0;
    sh[t] = v;
    __syncthreads();
    for (int off = 1; off < 512; off <<= 1) {
        int x = (t >= off) ? sh[t - off] : 0;
        __syncthreads();
        sh[t] += x;
        __syncthreads();
    }
    if (t < NB) g_bsum[t] = sh[t] - v;
}

__global__ void scan3() {
    int i = blockIdx.x * blockDim.x + threadIdx.x;
    if (i < NN) {
        int o = g_off[i] + g_bsum[i >> 8];
        g_off[i] = o;
        g_cursor[i] = o;
    }
}

__global__ void fill_kernel() {
    int e = blockIdx.x * blockDim.x + threadIdx.x;
    if (e >= NE) return;
    int s = g_src[e];
    int d = g_dst[e];
    if ((unsigned)s >= NN || (unsigned)d >= NN) return;
    int pos = atomicAdd(&g_cursor[d], 1);
    g_csr_src[pos] = s;
    g_csr_norm[pos] = g_dinv[s] * g_dinv[d];
}

// ---------------- GEMM: g_Ah[M,64](fp16) = X[M,K](fp32) @ W[K,64] ----------------
// 256 threads / 32 rows per block; thread computes 2 rows x 4 cols.
// Inner loop k-unrolled x4 with float4 loads for both X and W.

template <int K, bool FROMB>
__global__ __launch_bounds__(256) void gemm64(
    const float* __restrict__ Xin, const float* __restrict__ W, int M)
{
    constexpr int PAD = (K == 128) ? 0 : 4;   // keeps static smem <= 48KB at K=128
    const float* __restrict__ X = FROMB ? (const float*)g_B : Xin;
    __shared__ float Ws[K * 64];
    __shared__ float Xs[32 * (K + PAD)];
    const int tid = threadIdx.x;

    for (int i = tid; i < K * 64; i += 256) Ws[i] = W[i];
    const int r0 = blockIdx.x * 32;
    for (int i = tid; i < 32 * K; i += 256) {
        int r = i / K, k = i - r * K;
        int gr = r0 + r;
        Xs[r * (K + PAD) + k] = (gr < M) ? X[(size_t)gr * K + k] : 0.f;
    }
    __syncthreads();

    const int cx = tid & 15;
    const int ry = tid >> 4;
    const float4* x0p = (const float4*)&Xs[(2 * ry) * (K + PAD)];
    const float4* x1p = (const float4*)&Xs[(2 * ry + 1) * (K + PAD)];

    float4 a0 = make_float4(0.f, 0.f, 0.f, 0.f);
    float4 a1 = make_float4(0.f, 0.f, 0.f, 0.f);
#pragma unroll 8
    for (int kk = 0; kk < K / 4; kk++) {
        float4 xa = x0p[kk];
        float4 xb = x1p[kk];
        float4 w0 = *(const float4*)&Ws[(4 * kk + 0) * 64 + cx * 4];
        float4 w1 = *(const float4*)&Ws[(4 * kk + 1) * 64 + cx * 4];
        float4 w2 = *(const float4*)&Ws[(4 * kk + 2) * 64 + cx * 4];
        float4 w3 = *(const float4*)&Ws[(4 * kk + 3) * 64 + cx * 4];
        a0.x = fmaf(xa.x, w0.x, a0.x); a0.y = fmaf(xa.x, w0.y, a0.y);
        a0.z = fmaf(xa.x, w0.z, a0.z); a0.w = fmaf(xa.x, w0.w, a0.w);
        a1.x = fmaf(xb.x, w0.x, a1.x); a1.y = fmaf(xb.x, w0.y, a1.y);
        a1.z = fmaf(xb.x, w0.z, a1.z); a1.w = fmaf(xb.x, w0.w, a1.w);
        a0.x = fmaf(xa.y, w1.x, a0.x); a0.y = fmaf(xa.y, w1.y, a0.y);
        a0.z = fmaf(xa.y, w1.z, a0.z); a0.w = fmaf(xa.y, w1.w, a0.w);
        a1.x = fmaf(xb.y, w1.x, a1.x); a1.y = fmaf(xb.y, w1.y, a1.y);
        a1.z = fmaf(xb.y, w1.z, a1.z); a1.w = fmaf(xb.y, w1.w, a1.w);
        a0.x = fmaf(xa.z, w2.x, a0.x); a0.y = fmaf(xa.z, w2.y, a0.y);
        a0.z = fmaf(xa.z, w2.z, a0.z); a0.w = fmaf(xa.z, w2.w, a0.w);
        a1.x = fmaf(xb.z, w2.x, a1.x); a1.y = fmaf(xb.z, w2.y, a1.y);
        a1.z = fmaf(xb.z, w2.z, a1.z); a1.w = fmaf(xb.z, w2.w, a1.w);
        a0.x = fmaf(xa.w, w3.x, a0.x); a0.y = fmaf(xa.w, w3.y, a0.y);
        a0.z = fmaf(xa.w, w3.z, a0.z); a0.w = fmaf(xa.w, w3.w, a0.w);
        a1.x = fmaf(xb.w, w3.x, a1.x); a1.y = fmaf(xb.w, w3.y, a1.y);
        a1.z = fmaf(xb.w, w3.z, a1.z); a1.w = fmaf(xb.w, w3.w, a1.w);
    }
    const int r = r0 + 2 * ry;
    if (r < M) {
        g_Ah[(size_t)r * 32 + cx * 2]     = __floats2half2_rn(a0.x, a0.y);
        g_Ah[(size_t)r * 32 + cx * 2 + 1] = __floats2half2_rn(a0.z, a0.w);
    }
    if (r + 1 < M) {
        g_Ah[(size_t)(r + 1) * 32 + cx * 2]     = __floats2half2_rn(a1.x, a1.y);
        g_Ah[(size_t)(r + 1) * 32 + cx * 2 + 1] = __floats2half2_rn(a1.z, a1.w);
    }
}

// ---------------- Gather + self-loop + bias (+ReLU): g_B = conv(g_Ah) ----------------
// One warp per destination node; lane owns dims {2*lane, 2*lane+1} (one half2).
// Each edge row = 128 bytes = 1 cache line per warp.

__global__ __launch_bounds__(256) void gather_kernel(const float* __restrict__ b, int relu)
{
    int node = (blockIdx.x * blockDim.x + threadIdx.x) >> 5;
    int lane = threadIdx.x & 31;
    if (node >= NN) return;

    int beg = g_off[node];
    int end = beg + g_deg[node];

    float a0 = 0.f, a1 = 0.f;
    int s = 0; float nn = 0.f;
    if (beg < end) { s = g_csr_src[beg]; nn = g_csr_norm[beg]; }
    for (int j = beg; j < end; j++) {
        int s2 = 0; float nn2 = 0.f;
        if (j + 1 < end) { s2 = __ldg(&g_csr_src[j + 1]); nn2 = __ldg(&g_csr_norm[j + 1]); }
        float2 v = __half22float2(g_Ah[(size_t)s * 32 + lane]);
        a0 = fmaf(v.x, nn, a0);
        a1 = fmaf(v.y, nn, a1);
        s = s2; nn = nn2;
    }

    float di = g_dinv[node];
    float self = di * di;
    float2 vs = __half22float2(g_Ah[(size_t)node * 32 + lane]);
    a0 = fmaf(vs.x, self, a0) + b[2 * lane];
    a1 = fmaf(vs.y, self, a1) + b[2 * lane + 1];
    if (relu) { a0 = fmaxf(a0, 0.f); a1 = fmaxf(a1, 0.f); }

    *(float2*)&g_B[(size_t)node * 64 + 2 * lane] = make_float2(a0, a1);
}

// ---------------- Head: out = log_softmax(g_B @ Wl + bl) ----------------

__global__ __launch_bounds__(256) void head_kernel(
    const float* __restrict__ Wl, const float* __restrict__ bl,
    float* __restrict__ out, int M)
{
    __shared__ float Wls[64 * OUTD];
    __shared__ float bls[OUTD];
    __shared__ float rowS[8][64];
    const int tid = threadIdx.x;
    for (int i = tid; i < 64 * OUTD; i += 256) Wls[i] = Wl[i];
    if (tid < OUTD) bls[tid] = bl[tid];
    __syncthreads();

    const int w = tid >> 5, lane = tid & 31;
    const int row = blockIdx.x * 8 + w;
    if (row >= M) return;

    rowS[w][lane]      = g_B[(size_t)row * 64 + lane];
    rowS[w][32 + lane] = g_B[(size_t)row * 64 + 32 + lane];
    __syncwarp();

    float acc0 = bls[lane];
    float acc1 = (lane < 8) ? bls[32 + lane] : 0.f;
#pragma unroll
    for (int k = 0; k < 64; k++) {
        float ek = rowS[w][k];
        acc0 = fmaf(ek, Wls[k * OUTD + lane], acc0);
        if (lane < 8) acc1 = fmaf(ek, Wls[k * OUTD + 32 + lane], acc1);
    }

    float m = acc0;
    if (lane < 8) m = fmaxf(m, acc1);
#pragma unroll
    for (int off = 16; off; off >>= 1) m = fmaxf(m, __shfl_xor_sync(0xffffffffu, m, off));
    float sum = expf(acc0 - m) + ((lane < 8) ? expf(acc1 - m) : 0.f);
#pragma unroll
    for (int off = 16; off; off >>= 1) sum += __shfl_xor_sync(0xffffffffu, sum, off);
    float lse = m + logf(sum);

    out[(size_t)row * OUTD + lane] = acc0 - lse;
    if (lane < 8) out[(size_t)row * OUTD + 32 + lane] = acc1 - lse;
}

// ---------------- Launch ----------------

extern "C" void kernel_launch(void* const* d_in, const int* in_sizes, int n_in,
                              void* d_out, int out_size)
{
    const float* x  = (const float*)d_in[0];
    const void*  ei = d_in[1];
    const float* W1 = (const float*)d_in[2];
    const float* b1 = (const float*)d_in[3];
    const float* W2 = (const float*)d_in[4];
    const float* b2 = (const float*)d_in[5];
    const float* Wl = (const float*)d_in[6];
    const float* bl = (const float*)d_in[7];
    float* out = (float*)d_out;

    const int M = NN;
    const int NBLK = (NN + 255) / 256;
    const int EBLK = (NE + 255) / 256;

    // CSR build (graph shared by both layers)
    detect_kernel<<<1, 32>>>((const int*)ei);
    zero_deg<<<NBLK, 256>>>();
    convdeg_kernel<<<EBLK, 256>>>(ei);
    dinv_kernel<<<NBLK, 256>>>();
    scan1<<<NB, 256>>>();
    scan2<<<1, 512>>>();
    scan3<<<NBLK, 256>>>();
    fill_kernel<<<EBLK, 256>>>();

    // Layer 1
    gemm64<IN_DIM, false><<<(M + 31) / 32, 256>>>(x, W1, M);
    gather_kernel<<<(M * 32 + 255) / 256, 256>>>(b1, 1);

    // Layer 2
    gemm64<HID, true><<<(M + 31) / 32, 256>>>(nullptr, W2, M);
    gather_kernel<<<(M * 32 + 255) / 256, 256>>>(b2, 0);

    // Head
    head_kernel<<<(M + 7) / 8, 256>>>(Wl, bl, out, M);
}

// round 6
// speedup vs baseline: 1.0652x; 1.0556x over previous
#include <cuda_runtime.h>
#include <cuda_fp16.h>
#include <math.h>

#define NN 100000
#define NE 1600000
#define IN_DIM 128
#define HID 64
#define OUTD 40
#define NB ((NN + 255) / 256)   // 391 scan blocks

// Scratch — __device__ globals (no allocation APIs allowed).
__device__ __half2 g_Ah[NN * 32];    // GEMM output h in fp16 (64 dims = 32 half2)
__device__ float   g_B[NN * 64];     // conv output / GEMM input (fp32)
__device__ int     g_src[NE];
__device__ int     g_dst[NE];
__device__ int     g_deg[NN];
__device__ float   g_dinv[NN];
__device__ int     g_off[NN];        // CSR row offsets (exclusive)
__device__ int     g_cursor[NN];
__device__ int     g_bsum[512];
__device__ int     g_csr_src[NE];
__device__ float   g_csr_norm[NE];
__device__ int     g_is64;

// ---------------- zero deg + edge dtype detection (fused) ----------------
// int64 indices < 2^31 => every odd 32-bit word is 0; int32 uniform => ~never.
__global__ void zero_detect_kernel(const int* __restrict__ ei32) {
    int i = blockIdx.x * blockDim.x + threadIdx.x;
    if (i < NN) g_deg[i] = 0;
    if (blockIdx.x == 0 && threadIdx.x < 32) {
        int t = threadIdx.x;
        int zeros = 0;
        for (int k = t; k < 2048; k += 32)
            if (ei32[2 * k + 1] == 0) zeros++;
#pragma unroll
        for (int o = 16; o; o >>= 1) zeros += __shfl_xor_sync(0xffffffffu, zeros, o);
        if (t == 0) g_is64 = (zeros > 1536) ? 1 : 0;
    }
}

// ---------------- Fused convert + degree count ----------------
__global__ void convdeg_kernel(const void* __restrict__ ei) {
    int e = blockIdx.x * blockDim.x + threadIdx.x;
    if (e >= NE) return;
    int s, d;
    if (g_is64) {
        const long long* p = (const long long*)ei;
        s = (int)p[e];
        d = (int)p[(size_t)NE + e];
    } else {
        const int* p = (const int*)ei;
        s = p[e];
        d = p[NE + e];
    }
    g_src[e] = s;
    g_dst[e] = d;
    if ((unsigned)d < NN && (unsigned)s < NN) atomicAdd(&g_deg[d], 1);
}

// Exclusive scan of g_deg -> g_off (3 phases); scan1 also emits dinv.
__global__ void scan1() {
    __shared__ int sh[256];
    int t = threadIdx.x, i = blockIdx.x * 256 + t;
    int v = (i < NN) ? g_deg[i] : 0;
    if (i < NN) g_dinv[i] = rsqrtf((float)v + 1.0f);  // +1 = self-loop
    sh[t] = v;
    __syncthreads();
    for (int off = 1; off < 256; off <<= 1) {
        int x = (t >= off) ? sh[t - off] : 0;
        __syncthreads();
        sh[t] += x;
        __syncthreads();
    }
    if (i < NN) g_off[i] = sh[t] - v;
    if (t == 255) g_bsum[blockIdx.x] = sh[255];
}

__global__ void scan2() {
    __shared__ int sh[512];
    int t = threadIdx.x;
    int v = (t < NB) ? g_bsum[t] : 0;
    sh[t] = v;
    __syncthreads();
    for (int off = 1; off < 512; off <<= 1) {
        int x = (t >= off) ? sh[t - off] : 0;
        __syncthreads();
        sh[t] += x;
        __syncthreads();
    }
    if (t < NB) g_bsum[t] = sh[t] - v;
}

__global__ void scan3() {
    int i = blockIdx.x * blockDim.x + threadIdx.x;
    if (i < NN) {
        int o = g_off[i] + g_bsum[i >> 8];
        g_off[i] = o;
        g_cursor[i] = o;
    }
}

__global__ void fill_kernel() {
    int e = blockIdx.x * blockDim.x + threadIdx.x;
    if (e >= NE) return;
    int s = g_src[e];
    int d = g_dst[e];
    if ((unsigned)s >= NN || (unsigned)d >= NN) return;
    int pos = atomicAdd(&g_cursor[d], 1);
    g_csr_src[pos] = s;
    g_csr_norm[pos] = g_dinv[s] * g_dinv[d];
}

// ---------------- GEMM: g_Ah[M,64](fp16) = X[M,K](fp32) @ W[K,64] ----------------

template <int K, bool FROMB>
__global__ __launch_bounds__(256) void gemm64(
    const float* __restrict__ Xin, const float* __restrict__ W, int M)
{
    constexpr int PAD = (K == 128) ? 0 : 4;   // keeps static smem <= 48KB at K=128
    const float* __restrict__ X = FROMB ? (const float*)g_B : Xin;
    __shared__ float Ws[K * 64];
    __shared__ float Xs[32 * (K + PAD)];
    const int tid = threadIdx.x;

    for (int i = tid; i < K * 64; i += 256) Ws[i] = W[i];
    const int r0 = blockIdx.x * 32;
    for (int i = tid; i < 32 * K; i += 256) {
        int r = i / K, k = i - r * K;
        int gr = r0 + r;
        Xs[r * (K + PAD) + k] = (gr < M) ? X[(size_t)gr * K + k] : 0.f;
    }
    __syncthreads();

    const int cx = tid & 15;
    const int ry = tid >> 4;
    const float4* x0p = (const float4*)&Xs[(2 * ry) * (K + PAD)];
    const float4* x1p = (const float4*)&Xs[(2 * ry + 1) * (K + PAD)];

    float4 a0 = make_float4(0.f, 0.f, 0.f, 0.f);
    float4 a1 = make_float4(0.f, 0.f, 0.f, 0.f);
#pragma unroll 8
    for (int kk = 0; kk < K / 4; kk++) {
        float4 xa = x0p[kk];
        float4 xb = x1p[kk];
        float4 w0 = *(const float4*)&Ws[(4 * kk + 0) * 64 + cx * 4];
        float4 w1 = *(const float4*)&Ws[(4 * kk + 1) * 64 + cx * 4];
        float4 w2 = *(const float4*)&Ws[(4 * kk + 2) * 64 + cx * 4];
        float4 w3 = *(const float4*)&Ws[(4 * kk + 3) * 64 + cx * 4];
        a0.x = fmaf(xa.x, w0.x, a0.x); a0.y = fmaf(xa.x, w0.y, a0.y);
        a0.z = fmaf(xa.x, w0.z, a0.z); a0.w = fmaf(xa.x, w0.w, a0.w);
        a1.x = fmaf(xb.x, w0.x, a1.x); a1.y = fmaf(xb.x, w0.y, a1.y);
        a1.z = fmaf(xb.x, w0.z, a1.z); a1.w = fmaf(xb.x, w0.w, a1.w);
        a0.x = fmaf(xa.y, w1.x, a0.x); a0.y = fmaf(xa.y, w1.y, a0.y);
        a0.z = fmaf(xa.y, w1.z, a0.z); a0.w = fmaf(xa.y, w1.w, a0.w);
        a1.x = fmaf(xb.y, w1.x, a1.x); a1.y = fmaf(xb.y, w1.y, a1.y);
        a1.z = fmaf(xb.y, w1.z, a1.z); a1.w = fmaf(xb.y, w1.w, a1.w);
        a0.x = fmaf(xa.z, w2.x, a0.x); a0.y = fmaf(xa.z, w2.y, a0.y);
        a0.z = fmaf(xa.z, w2.z, a0.z); a0.w = fmaf(xa.z, w2.w, a0.w);
        a1.x = fmaf(xb.z, w2.x, a1.x); a1.y = fmaf(xb.z, w2.y, a1.y);
        a1.z = fmaf(xb.z, w2.z, a1.z); a1.w = fmaf(xb.z, w2.w, a1.w);
        a0.x = fmaf(xa.w, w3.x, a0.x); a0.y = fmaf(xa.w, w3.y, a0.y);
        a0.z = fmaf(xa.w, w3.z, a0.z); a0.w = fmaf(xa.w, w3.w, a0.w);
        a1.x = fmaf(xb.w, w3.x, a1.x); a1.y = fmaf(xb.w, w3.y, a1.y);
        a1.z = fmaf(xb.w, w3.z, a1.z); a1.w = fmaf(xb.w, w3.w, a1.w);
    }
    const int r = r0 + 2 * ry;
    if (r < M) {
        g_Ah[(size_t)r * 32 + cx * 2]     = __floats2half2_rn(a0.x, a0.y);
        g_Ah[(size_t)r * 32 + cx * 2 + 1] = __floats2half2_rn(a0.z, a0.w);
    }
    if (r + 1 < M) {
        g_Ah[(size_t)(r + 1) * 32 + cx * 2]     = __floats2half2_rn(a1.x, a1.y);
        g_Ah[(size_t)(r + 1) * 32 + cx * 2 + 1] = __floats2half2_rn(a1.z, a1.w);
    }
}

// ---------------- Gather + self-loop + bias (+ReLU): g_B = conv(g_Ah) ----------------
// One warp per destination node; lane owns dims {2*lane, 2*lane+1}.
// Edge loop processed in batches of 4 independent loads -> MLP >= 4.

__global__ __launch_bounds__(256) void gather_kernel(const float* __restrict__ b, int relu)
{
    int node = (blockIdx.x * blockDim.x + threadIdx.x) >> 5;
    int lane = threadIdx.x & 31;
    if (node >= NN) return;

    int j = g_off[node];
    int end = j + g_deg[node];

    float a0 = 0.f, a1 = 0.f;

    for (; j + 4 <= end; j += 4) {
        int s0 = __ldg(&g_csr_src[j]);
        int s1 = __ldg(&g_csr_src[j + 1]);
        int s2 = __ldg(&g_csr_src[j + 2]);
        int s3 = __ldg(&g_csr_src[j + 3]);
        float n0 = __ldg(&g_csr_norm[j]);
        float n1 = __ldg(&g_csr_norm[j + 1]);
        float n2 = __ldg(&g_csr_norm[j + 2]);
        float n3 = __ldg(&g_csr_norm[j + 3]);
        __half2 h0 = g_Ah[(size_t)s0 * 32 + lane];
        __half2 h1 = g_Ah[(size_t)s1 * 32 + lane];
        __half2 h2 = g_Ah[(size_t)s2 * 32 + lane];
        __half2 h3 = g_Ah[(size_t)s3 * 32 + lane];
        float2 v0 = __half22float2(h0);
        float2 v1 = __half22float2(h1);
        float2 v2 = __half22float2(h2);
        float2 v3 = __half22float2(h3);
        a0 = fmaf(v0.x, n0, a0); a1 = fmaf(v0.y, n0, a1);
        a0 = fmaf(v1.x, n1, a0); a1 = fmaf(v1.y, n1, a1);
        a0 = fmaf(v2.x, n2, a0); a1 = fmaf(v2.y, n2, a1);
        a0 = fmaf(v3.x, n3, a0); a1 = fmaf(v3.y, n3, a1);
    }
    for (; j < end; j++) {
        int s = __ldg(&g_csr_src[j]);
        float nn = __ldg(&g_csr_norm[j]);
        float2 v = __half22float2(g_Ah[(size_t)s * 32 + lane]);
        a0 = fmaf(v.x, nn, a0);
        a1 = fmaf(v.y, nn, a1);
    }

    float di = g_dinv[node];
    float self = di * di;
    float2 vs = __half22float2(g_Ah[(size_t)node * 32 + lane]);
    a0 = fmaf(vs.x, self, a0) + b[2 * lane];
    a1 = fmaf(vs.y, self, a1) + b[2 * lane + 1];
    if (relu) { a0 = fmaxf(a0, 0.f); a1 = fmaxf(a1, 0.f); }

    *(float2*)&g_B[(size_t)node * 64 + 2 * lane] = make_float2(a0, a1);
}

// ---------------- Head: out = log_softmax(g_B @ Wl + bl) ----------------

__global__ __launch_bounds__(256) void head_kernel(
    const float* __restrict__ Wl, const float* __restrict__ bl,
    float* __restrict__ out, int M)
{
    __shared__ float Wls[64 * OUTD];
    __shared__ float bls[OUTD];
    __shared__ float rowS[8][64];
    const int tid = threadIdx.x;
    for (int i = tid; i < 64 * OUTD; i += 256) Wls[i] = Wl[i];
    if (tid < OUTD) bls[tid] = bl[tid];
    __syncthreads();

    const int w = tid >> 5, lane = tid & 31;
    const int row = blockIdx.x * 8 + w;
    if (row >= M) return;

    rowS[w][lane]      = g_B[(size_t)row * 64 + lane];
    rowS[w][32 + lane] = g_B[(size_t)row * 64 + 32 + lane];
    __syncwarp();

    float acc0 = bls[lane];
    float acc1 = (lane < 8) ? bls[32 + lane] : 0.f;
#pragma unroll
    for (int k = 0; k < 64; k++) {
        float ek = rowS[w][k];
        acc0 = fmaf(ek, Wls[k * OUTD + lane], acc0);
        if (lane < 8) acc1 = fmaf(ek, Wls[k * OUTD + 32 + lane], acc1);
    }

    float m = acc0;
    if (lane < 8) m = fmaxf(m, acc1);
#pragma unroll
    for (int off = 16; off; off >>= 1) m = fmaxf(m, __shfl_xor_sync(0xffffffffu, m, off));
    float sum = expf(acc0 - m) + ((lane < 8) ? expf(acc1 - m) : 0.f);
#pragma unroll
    for (int off = 16; off; off >>= 1) sum += __shfl_xor_sync(0xffffffffu, sum, off);
    float lse = m + logf(sum);

    out[(size_t)row * OUTD + lane] = acc0 - lse;
    if (lane < 8) out[(size_t)row * OUTD + 32 + lane] = acc1 - lse;
}

// ---------------- Launch ----------------

extern "C" void kernel_launch(void* const* d_in, const int* in_sizes, int n_in,
                              void* d_out, int out_size)
{
    const float* x  = (const float*)d_in[0];
    const void*  ei = d_in[1];
    const float* W1 = (const float*)d_in[2];
    const float* b1 = (const float*)d_in[3];
    const float* W2 = (const float*)d_in[4];
    const float* b2 = (const float*)d_in[5];
    const float* Wl = (const float*)d_in[6];
    const float* bl = (const float*)d_in[7];
    float* out = (float*)d_out;

    const int M = NN;
    const int NBLK = (NN + 255) / 256;
    const int EBLK = (NE + 255) / 256;

    // CSR build (graph shared by both layers)
    zero_detect_kernel<<<NBLK, 256>>>((const int*)ei);
    convdeg_kernel<<<EBLK, 256>>>(ei);
    scan1<<<NB, 256>>>();
    scan2<<<1, 512>>>();
    scan3<<<NBLK, 256>>>();
    fill_kernel<<<EBLK, 256>>>();

    // Layer 1
    gemm64<IN_DIM, false><<<(M + 31) / 32, 256>>>(x, W1, M);
    gather_kernel<<<(M * 32 + 255) / 256, 256>>>(b1, 1);

    // Layer 2
    gemm64<HID, true><<<(M + 31) / 32, 256>>>(nullptr, W2, M);
    gather_kernel<<<(M * 32 + 255) / 256, 256>>>(b2, 0);

    // Head
    head_kernel<<<(M + 7) / 8, 256>>>(Wl, bl, out, M);
}